// round 3
// baseline (speedup 1.0000x reference)
#include <cuda_runtime.h>
#include <cstdint>

#define UNITS   2048
#define IN_DIM  512
#define TSTEPS  8192
#define NCTA    128
#define SCAN_THREADS 256

// 64 MB staging buffer for xin = x @ wax^T + ba
__device__ float g_xin[(size_t)TSTEPS * UNITS];
// per-CTA monotonic step stamps
__device__ unsigned g_flags[NCTA];

__device__ __forceinline__ unsigned ld_relaxed_gpu(const unsigned* p) {
    unsigned v;
    asm volatile("ld.relaxed.gpu.u32 %0, [%1];" : "=r"(v) : "l"(p) : "memory");
    return v;
}
__device__ __forceinline__ void st_release_gpu(unsigned* p, unsigned v) {
    asm volatile("st.release.gpu.u32 [%0], %1;" :: "l"(p), "r"(v) : "memory");
}
__device__ __forceinline__ void fence_acq_rel_gpu() {
    asm volatile("fence.acq_rel.gpu;" ::: "memory");
}
__device__ __forceinline__ unsigned long long ffma2(
    unsigned long long a, unsigned long long b, unsigned long long c) {
    unsigned long long d;
    asm("fma.rn.f32x2 %0, %1, %2, %3;" : "=l"(d) : "l"(a), "l"(b), "l"(c));
    return d;
}
__device__ __forceinline__ float pair_sum(unsigned long long p) {
    unsigned lo, hi;
    asm("mov.b64 {%0, %1}, %2;" : "=r"(lo), "=r"(hi) : "l"(p));
    return __uint_as_float(lo) + __uint_as_float(hi);
}

// ---------------------------------------------------------------------------
__global__ void init_kernel() {
    if (threadIdx.x < NCTA) g_flags[threadIdx.x] = 0u;
}

// ---------------------------------------------------------------------------
// Phase 1: xin[t][u] = sum_d x[t][d] * wax[u][d] + ba[u]
// ---------------------------------------------------------------------------
__global__ __launch_bounds__(256) void xin_gemm_kernel(
    const float* __restrict__ x,     // [8192][512]
    const float* __restrict__ wax,   // [2048][512]
    const float* __restrict__ ba)    // [2048]
{
    __shared__ float As[16][128 + 4];
    __shared__ float Bs[16][64 + 4];

    const int tid = threadIdx.x;
    const int bm = blockIdx.y * 128;
    const int bn = blockIdx.x * 64;
    const int tx = tid & 15;
    const int ty = tid >> 4;

    float acc[8][4];
#pragma unroll
    for (int i = 0; i < 8; i++)
#pragma unroll
        for (int j = 0; j < 4; j++) acc[i][j] = 0.f;

    const int lr = tid >> 2;
    const int lc = (tid & 3) * 4;

    for (int k0 = 0; k0 < IN_DIM; k0 += 16) {
        float4 a0 = *(const float4*)&x[(size_t)(bm + lr) * IN_DIM + k0 + lc];
        float4 a1 = *(const float4*)&x[(size_t)(bm + lr + 64) * IN_DIM + k0 + lc];
        float4 b0 = *(const float4*)&wax[(size_t)(bn + lr) * IN_DIM + k0 + lc];

        As[lc + 0][lr] = a0.x; As[lc + 1][lr] = a0.y;
        As[lc + 2][lr] = a0.z; As[lc + 3][lr] = a0.w;
        As[lc + 0][lr + 64] = a1.x; As[lc + 1][lr + 64] = a1.y;
        As[lc + 2][lr + 64] = a1.z; As[lc + 3][lr + 64] = a1.w;
        Bs[lc + 0][lr] = b0.x; Bs[lc + 1][lr] = b0.y;
        Bs[lc + 2][lr] = b0.z; Bs[lc + 3][lr] = b0.w;
        __syncthreads();

#pragma unroll
        for (int kk = 0; kk < 16; kk++) {
            float4 av0 = *(const float4*)&As[kk][ty * 8];
            float4 av1 = *(const float4*)&As[kk][ty * 8 + 4];
            float4 bv  = *(const float4*)&Bs[kk][tx * 4];
            float a[8] = {av0.x, av0.y, av0.z, av0.w, av1.x, av1.y, av1.z, av1.w};
            float b[4] = {bv.x, bv.y, bv.z, bv.w};
#pragma unroll
            for (int i = 0; i < 8; i++)
#pragma unroll
                for (int j = 0; j < 4; j++)
                    acc[i][j] = fmaf(a[i], b[j], acc[i][j]);
        }
        __syncthreads();
    }

    float4 bav = *(const float4*)&ba[bn + tx * 4];
#pragma unroll
    for (int i = 0; i < 8; i++) {
        float4 c;
        c.x = acc[i][0] + bav.x;
        c.y = acc[i][1] + bav.y;
        c.z = acc[i][2] + bav.z;
        c.w = acc[i][3] + bav.w;
        *(float4*)&g_xin[(size_t)(bm + ty * 8 + i) * UNITS + bn + tx * 4] = c;
    }
}

// ---------------------------------------------------------------------------
// Phase 2: persistent scan. 128 CTAs x 256 threads, 16 rows of waa per CTA.
// COLUMN-SPLIT layout: warp w owns ALL 16 rows x 256 columns
// [w*256, (w+1)*256). Each lane: 16 rows x 8 cols = 128 weights (64 f32x2
// pairs in regs). State is read straight from L2 (__ldcg), 8 KB/CTA/step,
// no SMEM staging. Packed fma.rn.f32x2 -> 64 FFMA2/lane/step.
// Reduction: value-halving shuffle fold (31 shfl) -> red_sm[8][16] ->
// warp0 sums 8 partials, tanh, 64B store. Relaxed flag polling by every
// warp + one acquire fence.
// ---------------------------------------------------------------------------
__global__ __launch_bounds__(SCAN_THREADS, 1) void scan_kernel(
    const float* __restrict__ waa,   // [2048][2048]
    float* __restrict__ out)         // [8192][2048]
{
    __shared__ float red_sm[8][16];

    const int tid  = threadIdx.x;
    const int lane = tid & 31;
    const int warp = tid >> 5;               // 0..7
    const int cta  = blockIdx.x;             // 0..127
    const int urow0 = cta * 16;              // this CTA's 16 output rows
    const int col0 = warp * 256 + lane * 8;  // this lane's 8 columns

    // Preload weights: wp[r][p] = waa[urow0+r][col0 + 2p .. 2p+1] packed
    unsigned long long wp[16][4];
#pragma unroll
    for (int r = 0; r < 16; r++) {
        const unsigned long long* wr =
            (const unsigned long long*)&waa[(size_t)(urow0 + r) * UNITS + col0];
#pragma unroll
        for (int p = 0; p < 4; p++) wp[r][p] = wr[p];
    }

    // poll pointers (4 flags per lane)
    const unsigned* fp0 = &g_flags[lane];
    const unsigned* fp1 = &g_flags[lane + 32];
    const unsigned* fp2 = &g_flags[lane + 64];
    const unsigned* fp3 = &g_flags[lane + 96];

    for (int t = 0; t < TSTEPS; t++) {
        // xin prefetch for the final reduction lanes (independent of state)
        float xv = 0.f;
        if (warp == 0 && lane < 16)
            xv = __ldg(&g_xin[(size_t)t * UNITS + urow0 + lane]);

        if (t > 0) {
            const unsigned target = (unsigned)t;
            for (;;) {
                unsigned f0 = ld_relaxed_gpu(fp0);
                unsigned f1 = ld_relaxed_gpu(fp1);
                unsigned f2 = ld_relaxed_gpu(fp2);
                unsigned f3 = ld_relaxed_gpu(fp3);
                unsigned m = min(min(f0, f1), min(f2, f3));
                if (__all_sync(0xffffffffu, m >= target)) break;
            }
            fence_acq_rel_gpu();

            // load this lane's 8 state values (L2, bypass L1)
            const unsigned long long* ap =
                (const unsigned long long*)(out + (size_t)(t - 1) * UNITS + col0);
            unsigned long long a0 = __ldcg(&ap[0]);
            unsigned long long a1 = __ldcg(&ap[1]);
            unsigned long long a2 = __ldcg(&ap[2]);
            unsigned long long a3 = __ldcg(&ap[3]);

            // 16 rows x 4 packed FFMA2, independent accumulator chains
            unsigned long long acc[16];
#pragma unroll
            for (int r = 0; r < 16; r++) {
                unsigned long long s = ffma2(wp[r][0], a0, 0ull);
                s = ffma2(wp[r][1], a1, s);
                s = ffma2(wp[r][2], a2, s);
                s = ffma2(wp[r][3], a3, s);
                acc[r] = s;
            }

            // collapse pairs -> 16 scalars
            float v16[16];
#pragma unroll
            for (int r = 0; r < 16; r++) v16[r] = pair_sum(acc[r]);

            // value-halving fold: 16+8+4+2+1 = 31 shfl
#pragma unroll
            for (int i = 0; i < 16; i++)
                v16[i] += __shfl_xor_sync(0xffffffffu, v16[i], 16);
            float v8[8];
            {
                const int o = (lane & 16) ? 8 : 0;
#pragma unroll
                for (int i = 0; i < 8; i++) v8[i] = v16[i + o];
            }
#pragma unroll
            for (int i = 0; i < 8; i++)
                v8[i] += __shfl_xor_sync(0xffffffffu, v8[i], 8);
            float v4[4];
            {
                const int o = (lane & 8) ? 4 : 0;
#pragma unroll
                for (int i = 0; i < 4; i++) v4[i] = v8[i + o];
            }
#pragma unroll
            for (int i = 0; i < 4; i++)
                v4[i] += __shfl_xor_sync(0xffffffffu, v4[i], 4);
            float v2[2];
            {
                const int o = (lane & 4) ? 2 : 0;
                v2[0] = v4[o]; v2[1] = v4[o + 1];
            }
#pragma unroll
            for (int i = 0; i < 2; i++)
                v2[i] += __shfl_xor_sync(0xffffffffu, v2[i], 2);
            float v1 = (lane & 2) ? v2[1] : v2[0];
            v1 += __shfl_xor_sync(0xffffffffu, v1, 1);

            const int r = ((lane & 16) ? 8 : 0) | ((lane & 8) ? 4 : 0) |
                          ((lane & 4) ? 2 : 0) | ((lane & 2) ? 1 : 0);
            if (!(lane & 1)) red_sm[warp][r] = v1;
        }

        __syncthreads();

        // final reduce + tanh + publish by warp0
        if (warp == 0 && lane < 16) {
            float s = xv;
            if (t > 0) {
#pragma unroll
                for (int w = 0; w < 8; w++) s += red_sm[w][lane];
            }
            out[(size_t)t * UNITS + urow0 + lane] = tanhf(s);
        }

        __syncthreads();   // red_sm reusable + stores done before release
        if (tid == 0)
            st_release_gpu(&g_flags[cta], (unsigned)(t + 1));
    }
}

// ---------------------------------------------------------------------------
extern "C" void kernel_launch(void* const* d_in, const int* in_sizes, int n_in,
                              void* d_out, int out_size) {
    const float* x   = (const float*)d_in[0];   // (1, 8192, 512)
    const float* waa = (const float*)d_in[1];   // (2048, 2048)
    const float* wax = (const float*)d_in[2];   // (2048, 512)
    const float* ba  = (const float*)d_in[3];   // (2048, 1)
    float* out = (float*)d_out;                 // (1, 8192, 2048)

    init_kernel<<<1, 128>>>();

    dim3 grid(UNITS / 64, TSTEPS / 128);        // (32, 64)
    xin_gemm_kernel<<<grid, 256>>>(x, wax, ba);

    scan_kernel<<<NCTA, SCAN_THREADS>>>(waa, out);
}

// round 6
// speedup vs baseline: 6.1379x; 6.1379x over previous
#include <cuda_runtime.h>
#include <cstdint>

#define UNITS   2048
#define IN_DIM  512
#define TSTEPS  8192
#define NCTA    128
#define SCAN_THREADS 256

// 64 MB staging buffer for xin = x @ wax^T + ba
__device__ float g_xin[(size_t)TSTEPS * UNITS];
// single counting barrier: each CTA adds 1 per completed step
__device__ unsigned g_ctr;

__device__ __forceinline__ unsigned ld_relaxed_gpu(const unsigned* p) {
    unsigned v;
    asm volatile("ld.relaxed.gpu.u32 %0, [%1];" : "=r"(v) : "l"(p) : "memory");
    return v;
}
__device__ __forceinline__ void red_release_add(unsigned* p, unsigned v) {
    asm volatile("red.release.gpu.global.add.u32 [%0], %1;"
                 :: "l"(p), "r"(v) : "memory");
}
__device__ __forceinline__ void fence_acq_rel_gpu() {
    asm volatile("fence.acq_rel.gpu;" ::: "memory");
}
__device__ __forceinline__ unsigned long long ffma2(
    unsigned long long a, unsigned long long b, unsigned long long c) {
    unsigned long long d;
    asm("fma.rn.f32x2 %0, %1, %2, %3;" : "=l"(d) : "l"(a), "l"(b), "l"(c));
    return d;
}
__device__ __forceinline__ unsigned long long packf2(float x, float y) {
    unsigned long long p;
    asm("mov.b64 %0, {%1, %2};" : "=l"(p) : "f"(x), "f"(y));
    return p;
}
__device__ __forceinline__ float pair_sum(unsigned long long p) {
    float lo, hi;
    asm("mov.b64 {%0, %1}, %2;" : "=f"(lo), "=f"(hi) : "l"(p));
    return lo + hi;
}

// ---------------------------------------------------------------------------
// Phase 1: xin[t][u] = sum_d x[t][d] * wax[u][d] + ba[u]
// block (0,0) also resets the scan barrier counter (runs before scan launch).
// ---------------------------------------------------------------------------
__global__ __launch_bounds__(256) void xin_gemm_kernel(
    const float* __restrict__ x,     // [8192][512]
    const float* __restrict__ wax,   // [2048][512]
    const float* __restrict__ ba)    // [2048]
{
    if (blockIdx.x == 0 && blockIdx.y == 0 && threadIdx.x == 0)
        g_ctr = 0u;

    __shared__ float As[16][128 + 4];
    __shared__ float Bs[16][64 + 4];

    const int tid = threadIdx.x;
    const int bm = blockIdx.y * 128;
    const int bn = blockIdx.x * 64;
    const int tx = tid & 15;
    const int ty = tid >> 4;

    float acc[8][4];
#pragma unroll
    for (int i = 0; i < 8; i++)
#pragma unroll
        for (int j = 0; j < 4; j++) acc[i][j] = 0.f;

    const int lr = tid >> 2;
    const int lc = (tid & 3) * 4;

    for (int k0 = 0; k0 < IN_DIM; k0 += 16) {
        float4 a0 = *(const float4*)&x[(size_t)(bm + lr) * IN_DIM + k0 + lc];
        float4 a1 = *(const float4*)&x[(size_t)(bm + lr + 64) * IN_DIM + k0 + lc];
        float4 b0 = *(const float4*)&wax[(size_t)(bn + lr) * IN_DIM + k0 + lc];

        As[lc + 0][lr] = a0.x; As[lc + 1][lr] = a0.y;
        As[lc + 2][lr] = a0.z; As[lc + 3][lr] = a0.w;
        As[lc + 0][lr + 64] = a1.x; As[lc + 1][lr + 64] = a1.y;
        As[lc + 2][lr + 64] = a1.z; As[lc + 3][lr + 64] = a1.w;
        Bs[lc + 0][lr] = b0.x; Bs[lc + 1][lr] = b0.y;
        Bs[lc + 2][lr] = b0.z; Bs[lc + 3][lr] = b0.w;
        __syncthreads();

#pragma unroll
        for (int kk = 0; kk < 16; kk++) {
            float4 av0 = *(const float4*)&As[kk][ty * 8];
            float4 av1 = *(const float4*)&As[kk][ty * 8 + 4];
            float4 bv  = *(const float4*)&Bs[kk][tx * 4];
            float a[8] = {av0.x, av0.y, av0.z, av0.w, av1.x, av1.y, av1.z, av1.w};
            float b[4] = {bv.x, bv.y, bv.z, bv.w};
#pragma unroll
            for (int i = 0; i < 8; i++)
#pragma unroll
                for (int j = 0; j < 4; j++)
                    acc[i][j] = fmaf(a[i], b[j], acc[i][j]);
        }
        __syncthreads();
    }

    float4 bav = *(const float4*)&ba[bn + tx * 4];
#pragma unroll
    for (int i = 0; i < 8; i++) {
        float4 c;
        c.x = acc[i][0] + bav.x;
        c.y = acc[i][1] + bav.y;
        c.z = acc[i][2] + bav.z;
        c.w = acc[i][3] + bav.w;
        *(float4*)&g_xin[(size_t)(bm + ty * 8 + i) * UNITS + bn + tx * 4] = c;
    }
}

// ---------------------------------------------------------------------------
// Phase 2: persistent scan (R1 layout + counting barrier + packed FMA).
// 128 CTAs x 256 threads; CTA owns 16 rows of waa, warp w owns rows
// {16*cta + 2w, +1}; lane holds cols {128k + 4*lane .. +3}, k=0..15, both
// rows, packed as f32x2 pairs (128 regs). Per step:
//   warp0: relaxed-poll single counter for 128*t, one acquire fence
//   -> __syncthreads -> all threads stage a_{t-1} (=out[t-1]) into SMEM
//   -> __syncthreads -> 64 FFMA2/lane (4 chains) -> 10-shfl butterfly
//   -> lane0: tanh x2, 8B store -> __syncthreads -> tid0: red.release.add.
// All reduce indices are compile-time: nothing can spill to local.
// ---------------------------------------------------------------------------
__global__ __launch_bounds__(SCAN_THREADS, 1) void scan_kernel(
    const float* __restrict__ waa,   // [2048][2048]
    float* __restrict__ out)         // [8192][2048]
{
    __shared__ float a_sm[UNITS];    // 8 KB state
    float4* a_sm4 = (float4*)a_sm;

    const int tid  = threadIdx.x;
    const int lane = tid & 31;
    const int warp = tid >> 5;               // 0..7
    const int cta  = blockIdx.x;             // 0..127
    const int row0 = cta * 16 + warp * 2;    // this warp's 2 output rows

    // Preload weights, packed as f32x2: w0/w1[k][0] = cols {4k*32+4l, +1},
    // [k][1] = cols {+2, +3}
    unsigned long long w0[16][2], w1[16][2];
#pragma unroll
    for (int k = 0; k < 16; k++) {
        float4 f0 = *(const float4*)&waa[(size_t)row0 * UNITS + k * 128 + lane * 4];
        float4 f1 = *(const float4*)&waa[(size_t)(row0 + 1) * UNITS + k * 128 + lane * 4];
        w0[k][0] = packf2(f0.x, f0.y); w0[k][1] = packf2(f0.z, f0.w);
        w1[k][0] = packf2(f1.x, f1.y); w1[k][1] = packf2(f1.z, f1.w);
    }

    for (int t = 0; t < TSTEPS; t++) {
        // lane0 prefetches this warp's xin pair (independent of the wait)
        float2 xv;
        if (lane == 0)
            xv = *(const float2*)&g_xin[(size_t)t * UNITS + row0];

        if (t > 0) {
            if (warp == 0) {
                const unsigned target = (unsigned)t * (unsigned)NCTA;
                while (ld_relaxed_gpu(&g_ctr) < target) { }
                fence_acq_rel_gpu();
            }
            __syncthreads();
            const float4* aprev = (const float4*)(out + (size_t)(t - 1) * UNITS);
            a_sm4[tid]       = aprev[tid];
            a_sm4[tid + 256] = aprev[tid + 256];
        } else {
            a_sm4[tid]       = make_float4(0.f, 0.f, 0.f, 0.f);
            a_sm4[tid + 256] = make_float4(0.f, 0.f, 0.f, 0.f);
        }
        __syncthreads();   // state staged

        // 2 rows x 2048 cols: 64 FFMA2 per lane, 4 independent chains
        unsigned long long acc0a = 0ull, acc0b = 0ull;
        unsigned long long acc1a = 0ull, acc1b = 0ull;
#pragma unroll
        for (int k = 0; k < 16; k++) {
            float4 av = a_sm4[k * 32 + lane];
            unsigned long long p0 = packf2(av.x, av.y);
            unsigned long long p1 = packf2(av.z, av.w);
            acc0a = ffma2(w0[k][0], p0, acc0a);
            acc0b = ffma2(w0[k][1], p1, acc0b);
            acc1a = ffma2(w1[k][0], p0, acc1a);
            acc1b = ffma2(w1[k][1], p1, acc1b);
        }
        float s0 = pair_sum(acc0a) + pair_sum(acc0b);
        float s1 = pair_sum(acc1a) + pair_sum(acc1b);

#pragma unroll
        for (int off = 16; off; off >>= 1) {
            s0 += __shfl_xor_sync(0xffffffffu, s0, off);
            s1 += __shfl_xor_sync(0xffffffffu, s1, off);
        }

        if (lane == 0) {
            float2 h;
            h.x = tanhf(s0 + xv.x);
            h.y = tanhf(s1 + xv.y);
            *(float2*)&out[(size_t)t * UNITS + row0] = h;
        }

        __syncthreads();   // all warps' stores done before the release
        if (tid == 0)
            red_release_add(&g_ctr, 1u);
    }
}

// ---------------------------------------------------------------------------
extern "C" void kernel_launch(void* const* d_in, const int* in_sizes, int n_in,
                              void* d_out, int out_size) {
    const float* x   = (const float*)d_in[0];   // (1, 8192, 512)
    const float* waa = (const float*)d_in[1];   // (2048, 2048)
    const float* wax = (const float*)d_in[2];   // (2048, 512)
    const float* ba  = (const float*)d_in[3];   // (2048, 1)
    float* out = (float*)d_out;                 // (1, 8192, 2048)

    dim3 grid(UNITS / 64, TSTEPS / 128);        // (32, 64)
    xin_gemm_kernel<<<grid, 256>>>(x, wax, ba); // also resets g_ctr

    scan_kernel<<<NCTA, SCAN_THREADS>>>(waa, out);
}